// round 2
// baseline (speedup 1.0000x reference)
#include <cuda_runtime.h>
#include <cstdint>

// Problem constants
#define BATCH 2
#define NCAM  6
#define DD    48
#define HH    28
#define WW    60
#define CC    64
#define GX    128
#define GY    128
#define GZ    4

// Per-(b,cam) projection matrix M (3x4): uvd = M @ [gx,gy,gz,1]
__device__ float g_M[BATCH * NCAM * 12];

// ---------------------------------------------------------------------------
// Kernel 1: M = K @ inv(lidar_to_sensor)[0:3, :]   (12 tiny matrices)
// ---------------------------------------------------------------------------
__global__ void prep_kernel(const float* __restrict__ intr,
                            const float* __restrict__ l2s) {
    int t = threadIdx.x;
    if (t >= BATCH * NCAM) return;
    const float* m = l2s + t * 16;   // row-major 4x4
    const float* K = intr + t * 9;   // row-major 3x3

    float inv[16];
    inv[0]  =  m[5]*m[10]*m[15] - m[5]*m[11]*m[14] - m[9]*m[6]*m[15] + m[9]*m[7]*m[14] + m[13]*m[6]*m[11] - m[13]*m[7]*m[10];
    inv[4]  = -m[4]*m[10]*m[15] + m[4]*m[11]*m[14] + m[8]*m[6]*m[15] - m[8]*m[7]*m[14] - m[12]*m[6]*m[11] + m[12]*m[7]*m[10];
    inv[8]  =  m[4]*m[9]*m[15]  - m[4]*m[11]*m[13] - m[8]*m[5]*m[15] + m[8]*m[7]*m[13] + m[12]*m[5]*m[11] - m[12]*m[7]*m[9];
    inv[12] = -m[4]*m[9]*m[14]  + m[4]*m[10]*m[13] + m[8]*m[5]*m[14] - m[8]*m[6]*m[13] - m[12]*m[5]*m[10] + m[12]*m[6]*m[9];
    inv[1]  = -m[1]*m[10]*m[15] + m[1]*m[11]*m[14] + m[9]*m[2]*m[15] - m[9]*m[3]*m[14] - m[13]*m[2]*m[11] + m[13]*m[3]*m[10];
    inv[5]  =  m[0]*m[10]*m[15] - m[0]*m[11]*m[14] - m[8]*m[2]*m[15] + m[8]*m[3]*m[14] + m[12]*m[2]*m[11] - m[12]*m[3]*m[10];
    inv[9]  = -m[0]*m[9]*m[15]  + m[0]*m[11]*m[13] + m[8]*m[1]*m[15] - m[8]*m[3]*m[13] - m[12]*m[1]*m[11] + m[12]*m[3]*m[9];
    inv[13] =  m[0]*m[9]*m[14]  - m[0]*m[10]*m[13] - m[8]*m[1]*m[14] + m[8]*m[2]*m[13] + m[12]*m[1]*m[10] - m[12]*m[2]*m[9];
    inv[2]  =  m[1]*m[6]*m[15]  - m[1]*m[7]*m[14]  - m[5]*m[2]*m[15] + m[5]*m[3]*m[14] + m[13]*m[2]*m[7]  - m[13]*m[3]*m[6];
    inv[6]  = -m[0]*m[6]*m[15]  + m[0]*m[7]*m[14]  + m[4]*m[2]*m[15] - m[4]*m[3]*m[14] - m[12]*m[2]*m[7]  + m[12]*m[3]*m[6];
    inv[10] =  m[0]*m[5]*m[15]  - m[0]*m[7]*m[13]  - m[4]*m[1]*m[15] + m[4]*m[3]*m[13] + m[12]*m[1]*m[7]  - m[12]*m[3]*m[5];
    inv[14] = -m[0]*m[5]*m[14]  + m[0]*m[6]*m[13]  + m[4]*m[1]*m[14] - m[4]*m[2]*m[13] - m[12]*m[1]*m[6]  + m[12]*m[2]*m[5];
    inv[3]  = -m[1]*m[6]*m[11]  + m[1]*m[7]*m[10]  + m[5]*m[2]*m[11] - m[5]*m[3]*m[10] - m[9]*m[2]*m[7]   + m[9]*m[3]*m[6];
    inv[7]  =  m[0]*m[6]*m[11]  - m[0]*m[7]*m[10]  - m[4]*m[2]*m[11] + m[4]*m[3]*m[10] + m[8]*m[2]*m[7]   - m[8]*m[3]*m[6];
    inv[11] = -m[0]*m[5]*m[11]  + m[0]*m[7]*m[9]   + m[4]*m[1]*m[11] - m[4]*m[3]*m[9]  - m[8]*m[1]*m[7]   + m[8]*m[3]*m[5];
    inv[15] =  m[0]*m[5]*m[10]  - m[0]*m[6]*m[9]   - m[4]*m[1]*m[10] + m[4]*m[2]*m[9]  + m[8]*m[1]*m[6]   - m[8]*m[2]*m[5];

    float det = m[0]*inv[0] + m[1]*inv[4] + m[2]*inv[8] + m[3]*inv[12];
    float rdet = 1.0f / det;
    #pragma unroll
    for (int i = 0; i < 16; i++) inv[i] *= rdet;

    float* M = g_M + t * 12;
    #pragma unroll
    for (int r = 0; r < 3; r++) {
        #pragma unroll
        for (int c = 0; c < 4; c++) {
            M[r * 4 + c] = K[r*3 + 0] * inv[0*4 + c]
                         + K[r*3 + 1] * inv[1*4 + c]
                         + K[r*3 + 2] * inv[2*4 + c];
        }
    }
}

// ---------------------------------------------------------------------------
// Kernel 2: BEV splat.
// Grid: (GX/32, GY, BATCH). Block: 256 threads.
//   lane (tid&31)  = x within 32-wide tile
//   warp (tid>>5)  = channel group cg (channels cg*8 .. cg*8+7)
// Phase 1: 768 projection tasks (32 x  x  24 cam/z combos) -> smem
// Phase 2: per-thread walk of 24 combos, expand valid trilinear corners
// Phase 3: coalesced stores (warp = fixed channel, lanes = consecutive x)
// ---------------------------------------------------------------------------
__global__ void __launch_bounds__(256)
bev_kernel(const float* __restrict__ frustum, float* __restrict__ out) {
    __shared__ float4 sm_combo[24 * 32];  // [combo][x] : ix, iy, iz, base(int)
    __shared__ float  sm_M[NCAM * 12];

    const int tid = threadIdx.x;
    const int b   = blockIdx.z;
    const int y   = blockIdx.y;
    const int x0t = blockIdx.x * 32;

    if (tid < NCAM * 12) sm_M[tid] = g_M[b * NCAM * 12 + tid];
    __syncthreads();

    const float gy = -47.625f + 0.75f * (float)y;

    // ---- Phase 1: projections ----
    #pragma unroll
    for (int t = tid; t < 768; t += 256) {
        const int xl    = t & 31;
        const int combo = t >> 5;         // cam*4 + z
        const int cam   = combo >> 2;
        const int zz    = combo & 3;
        const float gx = -47.625f + 0.75f * (float)(x0t + xl);
        const float gz = -3.0f + 2.0f * (float)zz;
        const float* M = &sm_M[cam * 12];
        const float u  = M[0]*gx + M[1]*gy + M[2]*gz  + M[3];
        const float v  = M[4]*gx + M[5]*gy + M[6]*gz  + M[7];
        const float d  = M[8]*gx + M[9]*gy + M[10]*gz + M[11];
        const float rd = 1.0f / d;
        const float ix = u * rd * ((float)(WW - 1) / (float)WW);
        const float iy = v * rd * ((float)(HH - 1) / (float)HH);
        const float iz = (d - 2.0f) * ((float)(DD - 1) / (float)DD);
        const bool ok = (ix > -1.0f) && (ix < (float)WW)
                     && (iy > -1.0f) && (iy < (float)HH)
                     && (iz > -1.0f) && (iz < (float)DD);
        const int base = ok ? (b * NCAM + cam) * (DD * HH * WW) : -1;  // pixel units
        sm_combo[combo * 32 + xl] = make_float4(ix, iy, iz, __int_as_float(base));
    }
    __syncthreads();

    const int lane = tid & 31;
    const int cg   = tid >> 5;

    float acc[8];
    #pragma unroll
    for (int j = 0; j < 8; j++) acc[j] = 0.0f;

    const float4* f4 = (const float4*)frustum;

    // ---- Phase 2: gather-accumulate ----
    #pragma unroll 1
    for (int combo = 0; combo < 24; combo++) {
        const float4 s = sm_combo[combo * 32 + lane];
        const int base = __float_as_int(s.w);
        if (base < 0) continue;

        const float fx0 = floorf(s.x); const int ix0 = (int)fx0; const float fx = s.x - fx0;
        const float fy0 = floorf(s.y); const int iy0 = (int)fy0; const float fy = s.y - fy0;
        const float fz0 = floorf(s.z); const int iz0 = (int)fz0; const float fz = s.z - fz0;

        const float wx0 = (ix0 >= 0)      ? (1.0f - fx) : 0.0f;
        const float wx1 = (ix0 <= WW - 2) ? fx          : 0.0f;
        const float wy0 = (iy0 >= 0)      ? (1.0f - fy) : 0.0f;
        const float wy1 = (iy0 <= HH - 2) ? fy          : 0.0f;
        const float wz0 = (iz0 >= 0)      ? (1.0f - fz) : 0.0f;
        const float wz1 = (iz0 <= DD - 2) ? fz          : 0.0f;

        #pragma unroll
        for (int dz = 0; dz < 2; dz++) {
            const float wz = dz ? wz1 : wz0;
            if (wz == 0.0f) continue;
            const int zoff = base + (iz0 + dz) * (HH * WW);
            #pragma unroll
            for (int dy = 0; dy < 2; dy++) {
                const float wzy = wz * (dy ? wy1 : wy0);
                if (wzy == 0.0f) continue;
                const int yoff = zoff + (iy0 + dy) * WW;
                #pragma unroll
                for (int dx = 0; dx < 2; dx++) {
                    const float w = wzy * (dx ? wx1 : wx0);
                    if (w == 0.0f) continue;
                    const int pix = yoff + (ix0 + dx);          // pixel index
                    const float4* p = f4 + (size_t)pix * (CC / 4) + cg * 2;
                    const float4 a = __ldg(p);
                    const float4 q = __ldg(p + 1);
                    acc[0] += w * a.x; acc[1] += w * a.y;
                    acc[2] += w * a.z; acc[3] += w * a.w;
                    acc[4] += w * q.x; acc[5] += w * q.y;
                    acc[6] += w * q.z; acc[7] += w * q.w;
                }
            }
        }
    }

    // ---- Phase 3: coalesced stores: out[b][c][y][x] ----
    const int xg = x0t + lane;
    size_t obase = (((size_t)b * CC + cg * 8) * GY + y) * GX + xg;
    #pragma unroll
    for (int j = 0; j < 8; j++) {
        out[obase + (size_t)j * (GY * GX)] = acc[j];
    }
}

extern "C" void kernel_launch(void* const* d_in, const int* in_sizes, int n_in,
                              void* d_out, int out_size) {
    const float* frustum = (const float*)d_in[0];
    const float* intr    = (const float*)d_in[1];
    const float* l2s     = (const float*)d_in[2];
    float* out = (float*)d_out;

    prep_kernel<<<1, 32>>>(intr, l2s);
    dim3 grid(GX / 32, GY, BATCH);
    bev_kernel<<<grid, 256>>>(frustum, out);
}

// round 6
// speedup vs baseline: 1.0135x; 1.0135x over previous
#include <cuda_runtime.h>
#include <cstdint>

// Problem constants
#define BATCH 2
#define NCAM  6
#define DD    48
#define HH    28
#define WW    60
#define CC    64
#define GX    128
#define GY    128
#define GZ    4

// ---------------------------------------------------------------------------
// Single fused kernel.
// Grid: (GX/32, GY, BATCH). Block: 256 threads.
//   lane (tid&31)  = x within 32-wide tile
//   warp (tid>>5)  = channel group cg (channels cg*8 .. cg*8+7)
// Phase 0: lanes 0..5 of warp 0 compute M = K @ inv(l2s)[0:3,:] for 6 cams
// Phase 1: 768 projection tasks (32 x  x  24 cam/z combos) -> smem
// Phase 1b: warp 0 compacts valid combos per lane (in-place, deterministic)
// Phase 2: per-thread loop over ONLY the valid entries for its lane
// Phase 3: coalesced stores (warp = fixed channel, lanes = consecutive x)
// ---------------------------------------------------------------------------
__global__ void __launch_bounds__(256)
bev_kernel(const float* __restrict__ frustum,
           const float* __restrict__ intr,
           const float* __restrict__ l2s,
           float* __restrict__ out) {
    __shared__ float4 sm_combo[24 * 32];   // [combo][x] : ix, iy, iz, base(int)
    __shared__ float  sm_M[NCAM * 12];
    __shared__ int    sm_cnt[32];

    const int tid = threadIdx.x;
    const int b   = blockIdx.z;
    const int y   = blockIdx.y;
    const int x0t = blockIdx.x * 32;

    // ---- Phase 0: per-block matrix prep (lanes 0..5 of warp 0) ----
    if (tid < NCAM) {
        const int idx = b * NCAM + tid;
        const float* m = l2s + idx * 16;   // row-major 4x4
        const float* K = intr + idx * 9;   // row-major 3x3

        float inv[16];
        inv[0]  =  m[5]*m[10]*m[15] - m[5]*m[11]*m[14] - m[9]*m[6]*m[15] + m[9]*m[7]*m[14] + m[13]*m[6]*m[11] - m[13]*m[7]*m[10];
        inv[4]  = -m[4]*m[10]*m[15] + m[4]*m[11]*m[14] + m[8]*m[6]*m[15] - m[8]*m[7]*m[14] - m[12]*m[6]*m[11] + m[12]*m[7]*m[10];
        inv[8]  =  m[4]*m[9]*m[15]  - m[4]*m[11]*m[13] - m[8]*m[5]*m[15] + m[8]*m[7]*m[13] + m[12]*m[5]*m[11] - m[12]*m[7]*m[9];
        inv[12] = -m[4]*m[9]*m[14]  + m[4]*m[10]*m[13] + m[8]*m[5]*m[14] - m[8]*m[6]*m[13] - m[12]*m[5]*m[10] + m[12]*m[6]*m[9];
        inv[1]  = -m[1]*m[10]*m[15] + m[1]*m[11]*m[14] + m[9]*m[2]*m[15] - m[9]*m[3]*m[14] - m[13]*m[2]*m[11] + m[13]*m[3]*m[10];
        inv[5]  =  m[0]*m[10]*m[15] - m[0]*m[11]*m[14] - m[8]*m[2]*m[15] + m[8]*m[3]*m[14] + m[12]*m[2]*m[11] - m[12]*m[3]*m[10];
        inv[9]  = -m[0]*m[9]*m[15]  + m[0]*m[11]*m[13] + m[8]*m[1]*m[15] - m[8]*m[3]*m[13] - m[12]*m[1]*m[11] + m[12]*m[3]*m[9];
        inv[13] =  m[0]*m[9]*m[14]  - m[0]*m[10]*m[13] - m[8]*m[1]*m[14] + m[8]*m[2]*m[13] + m[12]*m[1]*m[10] - m[12]*m[2]*m[9];
        inv[2]  =  m[1]*m[6]*m[15]  - m[1]*m[7]*m[14]  - m[5]*m[2]*m[15] + m[5]*m[3]*m[14] + m[13]*m[2]*m[7]  - m[13]*m[3]*m[6];
        inv[6]  = -m[0]*m[6]*m[15]  + m[0]*m[7]*m[14]  + m[4]*m[2]*m[15] - m[4]*m[3]*m[14] - m[12]*m[2]*m[7]  + m[12]*m[3]*m[6];
        inv[10] =  m[0]*m[5]*m[15]  - m[0]*m[7]*m[13]  - m[4]*m[1]*m[15] + m[4]*m[3]*m[13] + m[12]*m[1]*m[7]  - m[12]*m[3]*m[5];
        inv[14] = -m[0]*m[5]*m[14]  + m[0]*m[6]*m[13]  + m[4]*m[1]*m[14] - m[4]*m[2]*m[13] - m[12]*m[1]*m[6]  + m[12]*m[2]*m[5];
        inv[3]  = -m[1]*m[6]*m[11]  + m[1]*m[7]*m[10]  + m[5]*m[2]*m[11] - m[5]*m[3]*m[10] - m[9]*m[2]*m[7]   + m[9]*m[3]*m[6];
        inv[7]  =  m[0]*m[6]*m[11]  - m[0]*m[7]*m[10]  - m[4]*m[2]*m[11] + m[4]*m[3]*m[10] + m[8]*m[2]*m[7]   - m[8]*m[3]*m[6];
        inv[11] = -m[0]*m[5]*m[11]  + m[0]*m[7]*m[9]   + m[4]*m[1]*m[11] - m[4]*m[3]*m[9]  - m[8]*m[1]*m[7]   + m[8]*m[3]*m[5];
        inv[15] =  m[0]*m[5]*m[10]  - m[0]*m[6]*m[9]   - m[4]*m[1]*m[10] + m[4]*m[2]*m[9]  + m[8]*m[1]*m[6]   - m[8]*m[2]*m[5];

        float det = m[0]*inv[0] + m[1]*inv[4] + m[2]*inv[8] + m[3]*inv[12];
        float rdet = 1.0f / det;
        #pragma unroll
        for (int i = 0; i < 16; i++) inv[i] *= rdet;

        float* M = sm_M + tid * 12;
        #pragma unroll
        for (int r = 0; r < 3; r++) {
            #pragma unroll
            for (int c = 0; c < 4; c++) {
                M[r * 4 + c] = K[r*3 + 0] * inv[0*4 + c]
                             + K[r*3 + 1] * inv[1*4 + c]
                             + K[r*3 + 2] * inv[2*4 + c];
            }
        }
    }
    __syncthreads();

    const float gy = -47.625f + 0.75f * (float)y;

    // ---- Phase 1: projections ----
    #pragma unroll
    for (int t = tid; t < 768; t += 256) {
        const int xl    = t & 31;
        const int combo = t >> 5;         // cam*4 + z
        const int cam   = combo >> 2;
        const int zz    = combo & 3;
        const float gx = -47.625f + 0.75f * (float)(x0t + xl);
        const float gz = -3.0f + 2.0f * (float)zz;
        const float* M = &sm_M[cam * 12];
        const float u  = M[0]*gx + M[1]*gy + M[2]*gz  + M[3];
        const float v  = M[4]*gx + M[5]*gy + M[6]*gz  + M[7];
        const float d  = M[8]*gx + M[9]*gy + M[10]*gz + M[11];
        const float rd = 1.0f / d;
        const float ix = u * rd * ((float)(WW - 1) / (float)WW);
        const float iy = v * rd * ((float)(HH - 1) / (float)HH);
        const float iz = (d - 2.0f) * ((float)(DD - 1) / (float)DD);
        const bool ok = (ix > -1.0f) && (ix < (float)WW)
                     && (iy > -1.0f) && (iy < (float)HH)
                     && (iz > -1.0f) && (iz < (float)DD);
        const int base = ok ? (b * NCAM + cam) * (DD * HH * WW) : -1;  // pixel units
        sm_combo[combo * 32 + xl] = make_float4(ix, iy, iz, __int_as_float(base));
    }
    __syncthreads();

    // ---- Phase 1b: warp 0 compacts each lane's valid combos, in place ----
    // Forward compaction (write index <= read index) is hazard-free and
    // deterministic (combo-ordered), so FP accumulation order is fixed.
    if (tid < 32) {
        int cnt = 0;
        #pragma unroll
        for (int c = 0; c < 24; c++) {
            const float4 s = sm_combo[c * 32 + tid];
            if (__float_as_int(s.w) >= 0) {
                sm_combo[cnt * 32 + tid] = s;
                cnt++;
            }
        }
        sm_cnt[tid] = cnt;
    }
    __syncthreads();

    const int lane = tid & 31;
    const int cg   = tid >> 5;

    float acc[8];
    #pragma unroll
    for (int j = 0; j < 8; j++) acc[j] = 0.0f;

    const float4* f4 = (const float4*)frustum;
    const int n = sm_cnt[lane];

    // ---- Phase 2: gather-accumulate over valid entries only ----
    #pragma unroll 1
    for (int k = 0; k < n; k++) {
        const float4 s = sm_combo[k * 32 + lane];
        const int base = __float_as_int(s.w);

        const float fx0 = floorf(s.x); const int ix0 = (int)fx0; const float fx = s.x - fx0;
        const float fy0 = floorf(s.y); const int iy0 = (int)fy0; const float fy = s.y - fy0;
        const float fz0 = floorf(s.z); const int iz0 = (int)fz0; const float fz = s.z - fz0;

        const float wx0 = (ix0 >= 0)      ? (1.0f - fx) : 0.0f;
        const float wx1 = (ix0 <= WW - 2) ? fx          : 0.0f;
        const float wy0 = (iy0 >= 0)      ? (1.0f - fy) : 0.0f;
        const float wy1 = (iy0 <= HH - 2) ? fy          : 0.0f;
        const float wz0 = (iz0 >= 0)      ? (1.0f - fz) : 0.0f;
        const float wz1 = (iz0 <= DD - 2) ? fz          : 0.0f;

        #pragma unroll
        for (int dz = 0; dz < 2; dz++) {
            const float wz = dz ? wz1 : wz0;
            if (wz == 0.0f) continue;
            const int zoff = base + (iz0 + dz) * (HH * WW);
            #pragma unroll
            for (int dy = 0; dy < 2; dy++) {
                const float wzy = wz * (dy ? wy1 : wy0);
                if (wzy == 0.0f) continue;
                const int yoff = zoff + (iy0 + dy) * WW;
                #pragma unroll
                for (int dx = 0; dx < 2; dx++) {
                    const float w = wzy * (dx ? wx1 : wx0);
                    if (w == 0.0f) continue;
                    const int pix = yoff + (ix0 + dx);          // pixel index
                    const float4* p = f4 + (size_t)pix * (CC / 4) + cg * 2;
                    const float4 a = __ldg(p);
                    const float4 q = __ldg(p + 1);
                    acc[0] += w * a.x; acc[1] += w * a.y;
                    acc[2] += w * a.z; acc[3] += w * a.w;
                    acc[4] += w * q.x; acc[5] += w * q.y;
                    acc[6] += w * q.z; acc[7] += w * q.w;
                }
            }
        }
    }

    // ---- Phase 3: coalesced stores: out[b][c][y][x] ----
    const int xg = x0t + lane;
    size_t obase = (((size_t)b * CC + cg * 8) * GY + y) * GX + xg;
    #pragma unroll
    for (int j = 0; j < 8; j++) {
        out[obase + (size_t)j * (GY * GX)] = acc[j];
    }
}

extern "C" void kernel_launch(void* const* d_in, const int* in_sizes, int n_in,
                              void* d_out, int out_size) {
    const float* frustum = (const float*)d_in[0];
    const float* intr    = (const float*)d_in[1];
    const float* l2s     = (const float*)d_in[2];
    float* out = (float*)d_out;

    dim3 grid(GX / 32, GY, BATCH);
    bev_kernel<<<grid, 256>>>(frustum, intr, l2s, out);
}